// round 7
// baseline (speedup 1.0000x reference)
#include <cuda_runtime.h>
#include <math.h>

#define N_NODES 200000
#define N_EDGES 1250000
#define G 128
#define CAP 64
#define NTILES ((N_NODES + 255) / 256)   // 782

typedef unsigned long long ull;

// ---------------- device scratch (static; zero-initialized at load) ----------------
__device__ int   g_cnt[N_NODES];          // degree cursor; invariant: zero at call start
__device__ int   g_esrc[N_NODES * CAP];
__device__ float g_h1[N_NODES * 64];
__device__ float g_h2[N_NODES * 64];
__device__ float g_pool[G * 2 * 64];
__device__ int   g_gb[G + 1];

// ---------------- packed f32x2 helpers ----------------
__device__ __forceinline__ ull f32x2_dup(float x) {
    ull r;
    asm("mov.b64 %0, {%1, %1};" : "=l"(r) : "f"(x));
    return r;
}
__device__ __forceinline__ void f32x2_fma(ull& d, ull a, ull b) {
    asm("fma.rn.f32x2 %0, %1, %2, %0;" : "+l"(d) : "l"(a), "l"(b));
}
__device__ __forceinline__ float2 f32x2_unpack(ull a) {
    float lo, hi;
    asm("mov.b64 {%0, %1}, %2;" : "=f"(lo), "=f"(hi) : "l"(a));
    return make_float2(lo, hi);
}

// ---------------- scatter: bucket edges by dst (no scan needed) ----------------
__global__ void k_scatter(const int* __restrict__ e32) {
    __shared__ int s_is64;
    if (threadIdx.x == 0) {
        int all0 = 1;
        #pragma unroll 1
        for (int i = 0; i < 64; i++)
            if (e32[2 * i + 1] != 0) { all0 = 0; break; }
        s_is64 = all0;
    }
    __syncthreads();
    int e = blockIdx.x * blockDim.x + threadIdx.x;
    if (e >= N_EDGES) return;
    int src, dst;
    if (s_is64) {
        const long long* p = (const long long*)e32;
        src = (int)p[e]; dst = (int)p[N_EDGES + e];
    } else {
        src = e32[e]; dst = e32[N_EDGES + e];
    }
    int pos = atomicAdd(&g_cnt[dst], 1);
    if (pos < CAP) g_esrc[(dst << 6) + pos] = src;
}

// ---------------- graph segment boundaries (batch sorted; dtype from eidx) ----------------
__global__ void k_gb(const int* __restrict__ e32, const int* __restrict__ b32) {
    __shared__ int s_is64;
    if (threadIdx.x == 0) {
        int all0 = 1;
        #pragma unroll 1
        for (int i = 0; i < 64; i++)
            if (e32[2 * i + 1] != 0) { all0 = 0; break; }
        s_is64 = all0;
    }
    __syncthreads();
    int g = threadIdx.x;
    if (g > G) return;
    int lo = 0, hi = N_NODES;
    const long long* b64 = (const long long*)b32;
    while (lo < hi) {
        int mid = (lo + hi) >> 1;
        int bv = s_is64 ? (int)b64[mid] : b32[mid];
        if (bv < g) lo = mid + 1; else hi = mid;
    }
    g_gb[g] = lo;
}

// ---------------- fused GIN conv: gather + 2-layer MLP ----------------
// h = [relu]( relu( (x_i + sum_j x_j) @ w1 + b1 ) @ w2 + b2 )
// dynamic smem: w1s[4096] w2s[4096] b1s[64] b2s[64] zsh[256*65]
template <bool RELU_OUT>
__global__ void __launch_bounds__(256, 2) k_conv(const float* __restrict__ xin,
                                                 float* __restrict__ hout,
                                                 const float* __restrict__ w1,
                                                 const float* __restrict__ b1,
                                                 const float* __restrict__ w2,
                                                 const float* __restrict__ b2) {
    extern __shared__ float sm[];
    float* w1s = sm;
    float* w2s = sm + 4096;
    float* b1s = sm + 8192;
    float* b2s = sm + 8256;
    float* zsh = sm + 8320;          // 256 rows, stride 65 (conflict-free)

    int t = threadIdx.x, wid = t >> 5, lane = t & 31;
    {
        const float4* s1 = (const float4*)w1;
        const float4* s2 = (const float4*)w2;
        float4* d1 = (float4*)w1s;
        float4* d2 = (float4*)w2s;
        #pragma unroll
        for (int i = t; i < 1024; i += 256) { d1[i] = s1[i]; d2[i] = s2[i]; }
    }
    if (t < 64) { b1s[t] = b1[t]; b2s[t] = b2[t]; }

    const float2* __restrict__ x2 = (const float2*)xin;

    for (int tile = blockIdx.x; tile < NTILES; tile += gridDim.x) {
        int base = tile << 8;
        __syncthreads();   // weights ready (1st iter) / previous phase B done with zsh

        // ---- phase A: warp-per-node gather into smem z-tile ----
        #pragma unroll 1
        for (int j = 0; j < 32; j++) {
            int nl = (wid << 5) + j;
            int n = base + nl;
            if (n < N_NODES) {
                float2 a = x2[n * 32 + lane];
                int deg = g_cnt[n]; deg = min(deg, CAP);
                const int* es = g_esrc + (n << 6);
                int e = 0;
                for (; e + 4 <= deg; e += 4) {
                    int s0 = es[e + 0], s1 = es[e + 1];
                    int s2 = es[e + 2], s3 = es[e + 3];
                    float2 v0 = __ldg(&x2[s0 * 32 + lane]);
                    float2 v1 = __ldg(&x2[s1 * 32 + lane]);
                    float2 v2 = __ldg(&x2[s2 * 32 + lane]);
                    float2 v3 = __ldg(&x2[s3 * 32 + lane]);
                    a.x += (v0.x + v1.x) + (v2.x + v3.x);
                    a.y += (v0.y + v1.y) + (v2.y + v3.y);
                }
                for (; e < deg; e++) {
                    int s = es[e];
                    float2 v = __ldg(&x2[s * 32 + lane]);
                    a.x += v.x; a.y += v.y;
                }
                float* zr = zsh + nl * 65;
                zr[2 * lane]     = a.x;
                zr[2 * lane + 1] = a.y;
            }
        }
        __syncthreads();

        // ---- phase B: thread-per-node 2-layer MLP (f32x2 packed FMA) ----
        int n = base + t;
        if (n < N_NODES) {
            float* zr = zsh + t * 65;
            ull acc[32];

            // layer 1
            {
                const ull* bp = (const ull*)b1s;
                #pragma unroll
                for (int j = 0; j < 32; j++) acc[j] = bp[j];
                #pragma unroll 4
                for (int k = 0; k < 64; k++) {
                    ull zz = f32x2_dup(zr[k]);
                    const ulonglong2* wr = (const ulonglong2*)(w1s + (k << 6));
                    #pragma unroll
                    for (int j = 0; j < 16; j++) {
                        ulonglong2 w = wr[j];
                        f32x2_fma(acc[2 * j + 0], zz, w.x);
                        f32x2_fma(acc[2 * j + 1], zz, w.y);
                    }
                }
                #pragma unroll
                for (int j = 0; j < 32; j++) {
                    float2 p = f32x2_unpack(acc[j]);
                    zr[2 * j + 0] = fmaxf(p.x, 0.f);
                    zr[2 * j + 1] = fmaxf(p.y, 0.f);
                }
            }

            // layer 2
            {
                const ull* bp = (const ull*)b2s;
                #pragma unroll
                for (int j = 0; j < 32; j++) acc[j] = bp[j];
                #pragma unroll 4
                for (int k = 0; k < 64; k++) {
                    ull zz = f32x2_dup(zr[k]);
                    const ulonglong2* wr = (const ulonglong2*)(w2s + (k << 6));
                    #pragma unroll
                    for (int j = 0; j < 16; j++) {
                        ulonglong2 w = wr[j];
                        f32x2_fma(acc[2 * j + 0], zz, w.x);
                        f32x2_fma(acc[2 * j + 1], zz, w.y);
                    }
                }
            }

            float4* h4 = (float4*)(hout + n * 64);
            #pragma unroll
            for (int j = 0; j < 16; j++) {
                float2 p0 = f32x2_unpack(acc[2 * j + 0]);
                float2 p1 = f32x2_unpack(acc[2 * j + 1]);
                if (RELU_OUT) {
                    p0.x = fmaxf(p0.x, 0.f); p0.y = fmaxf(p0.y, 0.f);
                    p1.x = fmaxf(p1.x, 0.f); p1.y = fmaxf(p1.y, 0.f);
                }
                h4[j] = make_float4(p0.x, p0.y, p1.x, p1.y);
            }
        }
    }
}

// ---------------- pooling: per-graph sum & max (+ re-zero g_cnt invariant) ----------------
__global__ void __launch_bounds__(512) k_pool(const float* __restrict__ h) {
    // restore g_cnt = 0 for the next call (conv2 already consumed it)
    for (int i = blockIdx.x * blockDim.x + threadIdx.x; i < N_NODES;
         i += gridDim.x * blockDim.x)
        g_cnt[i] = 0;

    __shared__ float ssum[8][64], smax[8][64];
    int g = blockIdx.x, t = threadIdx.x;
    int col = t & 63, ch = t >> 6;
    int beg = g_gb[g], end = g_gb[g + 1];
    float s = 0.f, m = -INFINITY;
    for (int i = beg + ch; i < end; i += 8) {
        float v = h[i * 64 + col];
        s += v; m = fmaxf(m, v);
    }
    ssum[ch][col] = s; smax[ch][col] = m;
    __syncthreads();
    if (t < 64) {
        float S = 0.f, M = -INFINITY;
        #pragma unroll
        for (int c = 0; c < 8; c++) { S += ssum[c][t]; M = fmaxf(M, smax[c][t]); }
        g_pool[g * 128 + t]      = S;
        g_pool[g * 128 + 64 + t] = M;
    }
}

// ---------------- head MLP: 128 -> 128 -> 64 -> 32 -> 16 -> 1, SiLU ----------------
__device__ __forceinline__ float silu(float x) { return x / (1.f + expf(-x)); }

__global__ void __launch_bounds__(128) k_head(float* __restrict__ out,
        const float* __restrict__ w0, const float* __restrict__ b0,
        const float* __restrict__ w1, const float* __restrict__ b1,
        const float* __restrict__ w2, const float* __restrict__ b2,
        const float* __restrict__ w3, const float* __restrict__ b3,
        const float* __restrict__ w4, const float* __restrict__ b4) {
    __shared__ float bufA[128], bufB[128];
    int g = blockIdx.x, t = threadIdx.x;
    bufA[t] = g_pool[g * 128 + t];
    __syncthreads();
    {
        float a = b0[t];
        #pragma unroll 8
        for (int k = 0; k < 128; k++) a = fmaf(bufA[k], w0[k * 128 + t], a);
        bufB[t] = silu(a);
    }
    __syncthreads();
    if (t < 64) {
        float a = b1[t];
        #pragma unroll 8
        for (int k = 0; k < 128; k++) a = fmaf(bufB[k], w1[k * 64 + t], a);
        bufA[t] = silu(a);
    }
    __syncthreads();
    if (t < 32) {
        float a = b2[t];
        #pragma unroll 8
        for (int k = 0; k < 64; k++) a = fmaf(bufA[k], w2[k * 32 + t], a);
        bufB[t] = silu(a);
    }
    __syncthreads();
    if (t < 16) {
        float a = b3[t];
        #pragma unroll
        for (int k = 0; k < 32; k++) a = fmaf(bufB[k], w3[k * 16 + t], a);
        bufA[t] = silu(a);
    }
    __syncthreads();
    if (t == 0) {
        float a = b4[0];
        #pragma unroll
        for (int k = 0; k < 16; k++) a = fmaf(bufA[k], w4[k], a);
        out[g] = a;
    }
}

// ---------------- launch ----------------
extern "C" void kernel_launch(void* const* d_in, const int* in_sizes, int n_in,
                              void* d_out, int out_size) {
    const float* x     = (const float*)d_in[0];
    const int*   eidx  = (const int*)d_in[1];
    const int*   batch = (const int*)d_in[2];
    const float* c1w1 = (const float*)d_in[3];
    const float* c1b1 = (const float*)d_in[4];
    const float* c1w2 = (const float*)d_in[5];
    const float* c1b2 = (const float*)d_in[6];
    const float* c2w1 = (const float*)d_in[7];
    const float* c2b1 = (const float*)d_in[8];
    const float* c2w2 = (const float*)d_in[9];
    const float* c2b2 = (const float*)d_in[10];
    const float* hw0 = (const float*)d_in[11];
    const float* hb0 = (const float*)d_in[12];
    const float* hw1 = (const float*)d_in[13];
    const float* hb1 = (const float*)d_in[14];
    const float* hw2 = (const float*)d_in[15];
    const float* hb2 = (const float*)d_in[16];
    const float* hw3 = (const float*)d_in[17];
    const float* hb3 = (const float*)d_in[18];
    const float* hw4 = (const float*)d_in[19];
    const float* hb4 = (const float*)d_in[20];
    float* out = (float*)d_out;

    void *p1, *p2;
    cudaGetSymbolAddress(&p1, g_h1);
    cudaGetSymbolAddress(&p2, g_h2);
    float* h1 = (float*)p1;
    float* h2 = (float*)p2;

    const int convSmem = (8320 + 256 * 65) * (int)sizeof(float);   // 99840 B
    static int attrDone = 0;
    if (!attrDone) {
        cudaFuncSetAttribute(k_conv<true>,  cudaFuncAttributeMaxDynamicSharedMemorySize, convSmem);
        cudaFuncSetAttribute(k_conv<false>, cudaFuncAttributeMaxDynamicSharedMemorySize, convSmem);
        attrDone = 1;
    }

    const int EB = (N_EDGES + 255) / 256;   // 4883
    const int convGrid = 296;               // 2 blocks/SM * 148 SMs

    // launch index 3 (ncu capture slot) = conv2
    k_scatter<<<EB, 256>>>(eidx);                                           // 0
    k_gb<<<1, 256>>>(eidx, batch);                                          // 1
    k_conv<true><<<convGrid, 256, convSmem>>>(x, h1, c1w1, c1b1, c1w2, c1b2);   // 2
    k_conv<false><<<convGrid, 256, convSmem>>>(h1, h2, c2w1, c2b1, c2w2, c2b2); // 3
    k_pool<<<G, 512>>>(h2);                                                 // 4
    k_head<<<G, 128>>>(out, hw0, hb0, hw1, hb1, hw2, hb2, hw3, hb3, hw4, hb4); // 5
}

// round 9
// speedup vs baseline: 1.4701x; 1.4701x over previous
#include <cuda_runtime.h>
#include <cuda_bf16.h>
#include <math.h>
#include <stdint.h>

#define N_NODES 200000
#define N_EDGES 1250000
#define G 128
#define CAP 64
#define NT 1563            // ceil(N_NODES / 128)

// ---- dynamic smem byte offsets ----
// weight tiles: 64 rows x 72 halves (padded) x 2B = 9216 each
#define SM_W1H  0
#define SM_W1L  9216
#define SM_W2H  18432
#define SM_W2L  27648
// A tiles: 128 rows x 72 halves x 2B = 18432 each
#define SM_AH   36864
#define SM_AL   55296
#define SM_B1   73728
#define SM_B2   73984
#define SM_TOTAL 74240
#define ROWB 144           // padded row stride in bytes (72 halves)

// ---------------- device scratch (zero-initialized at load) ----------------
__device__ int   g_cnt[N_NODES];          // degree cursor; zero at call start
__device__ int   g_esrc[N_NODES * CAP];
__device__ float g_h1[N_NODES * 64];
__device__ float g_h2[N_NODES * 64];
__device__ float g_pool[G * 2 * 64];
__device__ int   g_gb[G + 1];

// ---------------- helpers ----------------
__device__ __forceinline__ uint32_t smem_u32(const void* p) {
    uint32_t a;
    asm("{ .reg .u64 t; cvta.to.shared.u64 t, %1; cvt.u32.u64 %0, t; }" : "=r"(a) : "l"(p));
    return a;
}
__device__ __forceinline__ void ldm_x4(uint32_t addr, uint32_t r[4]) {
    asm volatile("ldmatrix.sync.aligned.m8n8.x4.shared.b16 {%0,%1,%2,%3}, [%4];"
                 : "=r"(r[0]), "=r"(r[1]), "=r"(r[2]), "=r"(r[3]) : "r"(addr));
}
__device__ __forceinline__ void ldm_x2t(uint32_t addr, uint32_t& b0, uint32_t& b1) {
    asm volatile("ldmatrix.sync.aligned.m8n8.x2.trans.shared.b16 {%0,%1}, [%2];"
                 : "=r"(b0), "=r"(b1) : "r"(addr));
}
__device__ __forceinline__ void mma_bf16(float* c, const uint32_t a[4],
                                         uint32_t b0, uint32_t b1) {
    asm volatile("mma.sync.aligned.m16n8k16.row.col.f32.bf16.bf16.f32 "
                 "{%0,%1,%2,%3}, {%4,%5,%6,%7}, {%8,%9}, {%0,%1,%2,%3};"
                 : "+f"(c[0]), "+f"(c[1]), "+f"(c[2]), "+f"(c[3])
                 : "r"(a[0]), "r"(a[1]), "r"(a[2]), "r"(a[3]), "r"(b0), "r"(b1));
}
__device__ __forceinline__ void split_bf16(float v, uint16_t& hi, uint16_t& lo) {
    __nv_bfloat16 h = __float2bfloat16(v);
    float r = v - __bfloat162float(h);
    __nv_bfloat16 l = __float2bfloat16(r);
    hi = __bfloat16_as_ushort(h);
    lo = __bfloat16_as_ushort(l);
}
__device__ __forceinline__ uint32_t pack2(uint16_t a, uint16_t b) {
    return (uint32_t)a | ((uint32_t)b << 16);
}

// one 64x64 GEMM layer: acc[8][4] (f32 frags) = A(16x64, this warp's rows) @ W(64x64)
// 3-term hi/lo: Ah*Wh + Ah*Wl + Al*Wh
__device__ __forceinline__ void layer64(uint32_t aHi, uint32_t aLo,
                                        uint32_t wHi, uint32_t wLo,
                                        int lane, float acc[8][4]) {
    #pragma unroll
    for (int j = 0; j < 8; j++)
        #pragma unroll
        for (int q = 0; q < 4; q++) acc[j][q] = 0.f;

    uint32_t aOff = (uint32_t)(((lane & 7) + ((lane >> 3) & 1) * 8) * ROWB
                               + ((lane >> 4) * 8) * 2);
    #pragma unroll
    for (int kk = 0; kk < 4; kk++) {
        uint32_t ah[4], al[4];
        uint32_t ao = aOff + kk * 32;          // +16 halves per k-step
        ldm_x4(aHi + ao, ah);
        ldm_x4(aLo + ao, al);
        uint32_t brow = kk * 16 + (lane & 15);
        #pragma unroll
        for (int j = 0; j < 8; j++) {
            uint32_t bo = (brow * 72 + j * 8) * 2;
            uint32_t bh0, bh1, bl0, bl1;
            ldm_x2t(wHi + bo, bh0, bh1);
            ldm_x2t(wLo + bo, bl0, bl1);
            mma_bf16(acc[j], ah, bh0, bh1);
            mma_bf16(acc[j], ah, bl0, bl1);
            mma_bf16(acc[j], al, bh0, bh1);
        }
    }
}

// ---------------- scatter: bucket edges by dst ----------------
__global__ void k_scatter(const int* __restrict__ e32) {
    __shared__ int s_is64;
    if (threadIdx.x == 0) {
        int all0 = 1;
        #pragma unroll 1
        for (int i = 0; i < 64; i++)
            if (e32[2 * i + 1] != 0) { all0 = 0; break; }
        s_is64 = all0;
    }
    __syncthreads();
    int e = blockIdx.x * blockDim.x + threadIdx.x;
    if (e >= N_EDGES) return;
    int src, dst;
    if (s_is64) {
        const long long* p = (const long long*)e32;
        src = (int)p[e]; dst = (int)p[N_EDGES + e];
    } else {
        src = e32[e]; dst = e32[N_EDGES + e];
    }
    int pos = atomicAdd(&g_cnt[dst], 1);
    if (pos < CAP) g_esrc[(dst << 6) + pos] = src;
}

// ---------------- graph boundaries ----------------
__global__ void k_gb(const int* __restrict__ e32, const int* __restrict__ b32) {
    __shared__ int s_is64;
    if (threadIdx.x == 0) {
        int all0 = 1;
        #pragma unroll 1
        for (int i = 0; i < 64; i++)
            if (e32[2 * i + 1] != 0) { all0 = 0; break; }
        s_is64 = all0;
    }
    __syncthreads();
    int g = threadIdx.x;
    if (g > G) return;
    int lo = 0, hi = N_NODES;
    const long long* b64 = (const long long*)b32;
    while (lo < hi) {
        int mid = (lo + hi) >> 1;
        int bv = s_is64 ? (int)b64[mid] : b32[mid];
        if (bv < g) lo = mid + 1; else hi = mid;
    }
    g_gb[g] = lo;
}

// ---------------- fused GIN conv: gather + 2x mma.sync GEMM (warp-synchronous) ----------------
template <bool RELU_OUT>
__global__ void __launch_bounds__(256, 2)
k_conv(const float* __restrict__ xin, float* __restrict__ hout,
       const float* __restrict__ w1, const float* __restrict__ b1,
       const float* __restrict__ w2, const float* __restrict__ b2) {
    extern __shared__ char smc[];
    uint32_t sb = smem_u32(smc);
    int t = threadIdx.x, w = t >> 5, lane = t & 31;

    // ---- load weights once: split hi/lo into padded [k][n] tiles ----
    for (int idx = t; idx < 4096; idx += 256) {
        int k = idx >> 6, n = idx & 63;
        uint32_t off = (uint32_t)(k * 72 + n) * 2;
        uint16_t hi, lo;
        split_bf16(w1[idx], hi, lo);
        *(uint16_t*)(smc + SM_W1H + off) = hi;
        *(uint16_t*)(smc + SM_W1L + off) = lo;
        split_bf16(w2[idx], hi, lo);
        *(uint16_t*)(smc + SM_W2H + off) = hi;
        *(uint16_t*)(smc + SM_W2L + off) = lo;
    }
    if (t < 64) {
        ((float*)(smc + SM_B1))[t] = b1[t];
        ((float*)(smc + SM_B2))[t] = b2[t];
    }
    __syncthreads();   // weights/biases visible to all warps; only barrier needed

    const float* b1s = (const float*)(smc + SM_B1);
    const float* b2s = (const float*)(smc + SM_B2);
    const float2* __restrict__ x2 = (const float2*)xin;

    const uint32_t aHiW = sb + SM_AH + (uint32_t)(w * 16 * ROWB);   // this warp's 16 rows
    const uint32_t aLoW = sb + SM_AL + (uint32_t)(w * 16 * ROWB);
    char* aHiB = smc + SM_AH + w * 16 * ROWB;
    char* aLoB = smc + SM_AL + w * 16 * ROWB;

    int r0 = lane >> 2;                 // fragment row within 16
    int cq = (lane & 3) * 2;            // fragment col pair base within 8

    for (int tile = blockIdx.x; tile < NT; tile += gridDim.x) {
        int base = (tile << 7) + w * 16;    // this warp's first node

        // ---- gather: z = x_i + sum_j x_j, split hi/lo into own A rows ----
        #pragma unroll 1
        for (int i = 0; i < 16; i++) {
            int n = base + i;
            if (n < N_NODES) {
                float2 a = x2[n * 32 + lane];
                int deg = min(g_cnt[n], CAP);
                const int* es = g_esrc + (n << 6);
                int e = 0;
                for (; e + 4 <= deg; e += 4) {
                    int s0 = es[e + 0], s1 = es[e + 1];
                    int s2 = es[e + 2], s3 = es[e + 3];
                    float2 v0 = __ldg(&x2[s0 * 32 + lane]);
                    float2 v1 = __ldg(&x2[s1 * 32 + lane]);
                    float2 v2 = __ldg(&x2[s2 * 32 + lane]);
                    float2 v3 = __ldg(&x2[s3 * 32 + lane]);
                    a.x += (v0.x + v1.x) + (v2.x + v3.x);
                    a.y += (v0.y + v1.y) + (v2.y + v3.y);
                }
                for (; e < deg; e++) {
                    float2 v = __ldg(&x2[es[e] * 32 + lane]);
                    a.x += v.x; a.y += v.y;
                }
                uint16_t h0, l0, h1, l1;
                split_bf16(a.x, h0, l0);
                split_bf16(a.y, h1, l1);
                *(uint32_t*)(aHiB + i * ROWB + lane * 4) = pack2(h0, h1);
                *(uint32_t*)(aLoB + i * ROWB + lane * 4) = pack2(l0, l1);
            }
        }
        __syncwarp();

        // ---- layer 1 ----
        float acc[8][4];
        layer64(aHiW, aLoW, sb + SM_W1H, sb + SM_W1L, lane, acc);

        // epilogue 1: bias + relu, split back into own A rows
        #pragma unroll
        for (int j = 0; j < 8; j++) {
            int cb = j * 8 + cq;
            float v0 = fmaxf(acc[j][0] + b1s[cb],     0.f);
            float v1 = fmaxf(acc[j][1] + b1s[cb + 1], 0.f);
            float v2 = fmaxf(acc[j][2] + b1s[cb],     0.f);
            float v3 = fmaxf(acc[j][3] + b1s[cb + 1], 0.f);
            uint16_t h0, l0, h1, l1, h2, l2, h3, l3;
            split_bf16(v0, h0, l0); split_bf16(v1, h1, l1);
            split_bf16(v2, h2, l2); split_bf16(v3, h3, l3);
            *(uint32_t*)(aHiB + r0 * ROWB + cb * 2)       = pack2(h0, h1);
            *(uint32_t*)(aLoB + r0 * ROWB + cb * 2)       = pack2(l0, l1);
            *(uint32_t*)(aHiB + (r0 + 8) * ROWB + cb * 2) = pack2(h2, h3);
            *(uint32_t*)(aLoB + (r0 + 8) * ROWB + cb * 2) = pack2(l2, l3);
        }
        __syncwarp();

        // ---- layer 2 ----
        layer64(aHiW, aLoW, sb + SM_W2H, sb + SM_W2L, lane, acc);

        // epilogue 2: bias (+relu) -> gmem f32
        int n0 = base + r0;
        int n1 = n0 + 8;
        #pragma unroll
        for (int j = 0; j < 8; j++) {
            int cb = j * 8 + cq;
            float v0 = acc[j][0] + b2s[cb];
            float v1 = acc[j][1] + b2s[cb + 1];
            float v2 = acc[j][2] + b2s[cb];
            float v3 = acc[j][3] + b2s[cb + 1];
            if (RELU_OUT) {
                v0 = fmaxf(v0, 0.f); v1 = fmaxf(v1, 0.f);
                v2 = fmaxf(v2, 0.f); v3 = fmaxf(v3, 0.f);
            }
            if (n0 < N_NODES) *(float2*)(hout + n0 * 64 + cb) = make_float2(v0, v1);
            if (n1 < N_NODES) *(float2*)(hout + n1 * 64 + cb) = make_float2(v2, v3);
        }
        __syncwarp();
    }
}

// ---------------- pooling (+ re-zero g_cnt) ----------------
__global__ void __launch_bounds__(512) k_pool(const float* __restrict__ h) {
    for (int i = blockIdx.x * blockDim.x + threadIdx.x; i < N_NODES;
         i += gridDim.x * blockDim.x)
        g_cnt[i] = 0;

    __shared__ float ssum[8][64], smax[8][64];
    int g = blockIdx.x, t = threadIdx.x;
    int col = t & 63, ch = t >> 6;
    int beg = g_gb[g], end = g_gb[g + 1];
    float s = 0.f, m = -INFINITY;
    for (int i = beg + ch; i < end; i += 8) {
        float v = h[i * 64 + col];
        s += v; m = fmaxf(m, v);
    }
    ssum[ch][col] = s; smax[ch][col] = m;
    __syncthreads();
    if (t < 64) {
        float S = 0.f, M = -INFINITY;
        #pragma unroll
        for (int c = 0; c < 8; c++) { S += ssum[c][t]; M = fmaxf(M, smax[c][t]); }
        g_pool[g * 128 + t]      = S;
        g_pool[g * 128 + 64 + t] = M;
    }
}

// ---------------- head MLP ----------------
__device__ __forceinline__ float silu(float x) { return x / (1.f + expf(-x)); }

__global__ void __launch_bounds__(128) k_head(float* __restrict__ out,
        const float* __restrict__ w0, const float* __restrict__ b0,
        const float* __restrict__ w1, const float* __restrict__ b1,
        const float* __restrict__ w2, const float* __restrict__ b2,
        const float* __restrict__ w3, const float* __restrict__ b3,
        const float* __restrict__ w4, const float* __restrict__ b4) {
    __shared__ float bufA[128], bufB[128];
    int g = blockIdx.x, t = threadIdx.x;
    bufA[t] = g_pool[g * 128 + t];
    __syncthreads();
    {
        float a = b0[t];
        #pragma unroll 8
        for (int k = 0; k < 128; k++) a = fmaf(bufA[k], w0[k * 128 + t], a);
        bufB[t] = silu(a);
    }
    __syncthreads();
    if (t < 64) {
        float a = b1[t];
        #pragma unroll 8
        for (int k = 0; k < 128; k++) a = fmaf(bufB[k], w1[k * 64 + t], a);
        bufA[t] = silu(a);
    }
    __syncthreads();
    if (t < 32) {
        float a = b2[t];
        #pragma unroll 8
        for (int k = 0; k < 64; k++) a = fmaf(bufA[k], w2[k * 32 + t], a);
        bufB[t] = silu(a);
    }
    __syncthreads();
    if (t < 16) {
        float a = b3[t];
        #pragma unroll
        for (int k = 0; k < 32; k++) a = fmaf(bufB[k], w3[k * 16 + t], a);
        bufA[t] = silu(a);
    }
    __syncthreads();
    if (t == 0) {
        float a = b4[0];
        #pragma unroll
        for (int k = 0; k < 16; k++) a = fmaf(bufA[k], w4[k], a);
        out[g] = a;
    }
}

// ---------------- launch ----------------
extern "C" void kernel_launch(void* const* d_in, const int* in_sizes, int n_in,
                              void* d_out, int out_size) {
    const float* x     = (const float*)d_in[0];
    const int*   eidx  = (const int*)d_in[1];
    const int*   batch = (const int*)d_in[2];
    const float* c1w1 = (const float*)d_in[3];
    const float* c1b1 = (const float*)d_in[4];
    const float* c1w2 = (const float*)d_in[5];
    const float* c1b2 = (const float*)d_in[6];
    const float* c2w1 = (const float*)d_in[7];
    const float* c2b1 = (const float*)d_in[8];
    const float* c2w2 = (const float*)d_in[9];
    const float* c2b2 = (const float*)d_in[10];
    const float* hw0 = (const float*)d_in[11];
    const float* hb0 = (const float*)d_in[12];
    const float* hw1 = (const float*)d_in[13];
    const float* hb1 = (const float*)d_in[14];
    const float* hw2 = (const float*)d_in[15];
    const float* hb2 = (const float*)d_in[16];
    const float* hw3 = (const float*)d_in[17];
    const float* hb3 = (const float*)d_in[18];
    const float* hw4 = (const float*)d_in[19];
    const float* hb4 = (const float*)d_in[20];
    float* out = (float*)d_out;

    void *p1, *p2;
    cudaGetSymbolAddress(&p1, g_h1);
    cudaGetSymbolAddress(&p2, g_h2);
    float* h1 = (float*)p1;
    float* h2 = (float*)p2;

    static int attrDone = 0;
    if (!attrDone) {
        cudaFuncSetAttribute(k_conv<true>,  cudaFuncAttributeMaxDynamicSharedMemorySize, SM_TOTAL);
        cudaFuncSetAttribute(k_conv<false>, cudaFuncAttributeMaxDynamicSharedMemorySize, SM_TOTAL);
        attrDone = 1;
    }

    const int EB = (N_EDGES + 255) / 256;
    const int convGrid = 296;   // 2 CTAs/SM, grid-stride over 1563 tiles

    k_scatter<<<EB, 256>>>(eidx);                                               // 0
    k_gb<<<1, 256>>>(eidx, batch);                                              // 1
    k_conv<true><<<convGrid, 256, SM_TOTAL>>>(x, h1, c1w1, c1b1, c1w2, c1b2);   // 2
    k_conv<false><<<convGrid, 256, SM_TOTAL>>>(h1, h2, c2w1, c2b1, c2w2, c2b2); // 3
    k_pool<<<G, 512>>>(h2);                                                     // 4
    k_head<<<G, 128>>>(out, hw0, hb0, hw1, hb1, hw2, hb2, hw3, hb3, hw4, hb4);  // 5
}

// round 10
// speedup vs baseline: 1.7334x; 1.1791x over previous
#include <cuda_runtime.h>
#include <cuda_bf16.h>
#include <math.h>
#include <stdint.h>

#define N_NODES 200000
#define N_EDGES 1250000
#define G 128
#define CAP 64
#define NT 1563            // ceil(N_NODES / 128)

// ---- dynamic smem byte offsets ----
#define SM_W1H  0
#define SM_W1L  9216
#define SM_W2H  18432
#define SM_W2L  27648
#define SM_AH   36864
#define SM_AL   55296
#define SM_B1   73728
#define SM_B2   73984
#define SM_TOTAL 74240
#define ROWB 144           // padded row stride in bytes (72 halves)

// ---------------- device scratch (zero-initialized at load) ----------------
__device__ int   g_cnt[N_NODES];          // degree cursor; zero at call start
__device__ int   g_esrc[N_NODES * CAP];
__device__ float g_h1[N_NODES * 64];
__device__ float g_h2[N_NODES * 64];
__device__ float g_pool[G * 2 * 64];
__device__ int   g_gb[G + 1];

// ---------------- helpers ----------------
__device__ __forceinline__ uint32_t smem_u32(const void* p) {
    uint32_t a;
    asm("{ .reg .u64 t; cvta.to.shared.u64 t, %1; cvt.u32.u64 %0, t; }" : "=r"(a) : "l"(p));
    return a;
}
__device__ __forceinline__ void ldm_x4(uint32_t addr, uint32_t r[4]) {
    asm volatile("ldmatrix.sync.aligned.m8n8.x4.shared.b16 {%0,%1,%2,%3}, [%4];"
                 : "=r"(r[0]), "=r"(r[1]), "=r"(r[2]), "=r"(r[3]) : "r"(addr));
}
__device__ __forceinline__ void ldm_x2t(uint32_t addr, uint32_t& b0, uint32_t& b1) {
    asm volatile("ldmatrix.sync.aligned.m8n8.x2.trans.shared.b16 {%0,%1}, [%2];"
                 : "=r"(b0), "=r"(b1) : "r"(addr));
}
__device__ __forceinline__ void mma_bf16(float* c, const uint32_t a[4],
                                         uint32_t b0, uint32_t b1) {
    asm volatile("mma.sync.aligned.m16n8k16.row.col.f32.bf16.bf16.f32 "
                 "{%0,%1,%2,%3}, {%4,%5,%6,%7}, {%8,%9}, {%0,%1,%2,%3};"
                 : "+f"(c[0]), "+f"(c[1]), "+f"(c[2]), "+f"(c[3])
                 : "r"(a[0]), "r"(a[1]), "r"(a[2]), "r"(a[3]), "r"(b0), "r"(b1));
}
__device__ __forceinline__ void split_bf16(float v, uint16_t& hi, uint16_t& lo) {
    __nv_bfloat16 h = __float2bfloat16(v);
    float r = v - __bfloat162float(h);
    __nv_bfloat16 l = __float2bfloat16(r);
    hi = __bfloat16_as_ushort(h);
    lo = __bfloat16_as_ushort(l);
}
__device__ __forceinline__ uint32_t pack2(uint16_t a, uint16_t b) {
    return (uint32_t)a | ((uint32_t)b << 16);
}

// one 64x64 GEMM layer: acc[8][4] = A(16x64, this warp's rows) @ W(64x64)
// 3-term hi/lo: Ah*Wh + Ah*Wl + Al*Wh
__device__ __forceinline__ void layer64(uint32_t aHi, uint32_t aLo,
                                        uint32_t wHi, uint32_t wLo,
                                        int lane, float acc[8][4]) {
    #pragma unroll
    for (int j = 0; j < 8; j++)
        #pragma unroll
        for (int q = 0; q < 4; q++) acc[j][q] = 0.f;

    uint32_t aOff = (uint32_t)(((lane & 7) + ((lane >> 3) & 1) * 8) * ROWB
                               + ((lane >> 4) * 8) * 2);
    #pragma unroll
    for (int kk = 0; kk < 4; kk++) {
        uint32_t ah[4], al[4];
        uint32_t ao = aOff + kk * 32;          // +16 halves per k-step
        ldm_x4(aHi + ao, ah);
        ldm_x4(aLo + ao, al);
        uint32_t brow = kk * 16 + (lane & 15);
        #pragma unroll
        for (int j = 0; j < 8; j++) {
            uint32_t bo = (brow * 72 + j * 8) * 2;
            uint32_t bh0, bh1, bl0, bl1;
            ldm_x2t(wHi + bo, bh0, bh1);
            ldm_x2t(wLo + bo, bl0, bl1);
            mma_bf16(acc[j], ah, bh0, bh1);
            mma_bf16(acc[j], ah, bl0, bl1);
            mma_bf16(acc[j], al, bh0, bh1);
        }
    }
}

// ---------------- scatter: bucket edges by dst ----------------
__global__ void k_scatter(const int* __restrict__ e32) {
    __shared__ int s_is64;
    if (threadIdx.x == 0) {
        int all0 = 1;
        #pragma unroll 1
        for (int i = 0; i < 64; i++)
            if (e32[2 * i + 1] != 0) { all0 = 0; break; }
        s_is64 = all0;
    }
    __syncthreads();
    int e = blockIdx.x * blockDim.x + threadIdx.x;
    if (e >= N_EDGES) return;
    int src, dst;
    if (s_is64) {
        const long long* p = (const long long*)e32;
        src = (int)p[e]; dst = (int)p[N_EDGES + e];
    } else {
        src = e32[e]; dst = e32[N_EDGES + e];
    }
    int pos = atomicAdd(&g_cnt[dst], 1);
    if (pos < CAP) g_esrc[(dst << 6) + pos] = src;
}

// ---------------- graph boundaries ----------------
__global__ void k_gb(const int* __restrict__ e32, const int* __restrict__ b32) {
    __shared__ int s_is64;
    if (threadIdx.x == 0) {
        int all0 = 1;
        #pragma unroll 1
        for (int i = 0; i < 64; i++)
            if (e32[2 * i + 1] != 0) { all0 = 0; break; }
        s_is64 = all0;
    }
    __syncthreads();
    int g = threadIdx.x;
    if (g > G) return;
    int lo = 0, hi = N_NODES;
    const long long* b64 = (const long long*)b32;
    while (lo < hi) {
        int mid = (lo + hi) >> 1;
        int bv = s_is64 ? (int)b64[mid] : b32[mid];
        if (bv < g) lo = mid + 1; else hi = mid;
    }
    g_gb[g] = lo;
}

// ---------------- fused GIN conv (warp-synchronous, short gather chains) ----------------
template <bool RELU_OUT>
__global__ void __launch_bounds__(256, 3)
k_conv(const float* __restrict__ xin, float* __restrict__ hout,
       const float* __restrict__ w1, const float* __restrict__ b1,
       const float* __restrict__ w2, const float* __restrict__ b2) {
    extern __shared__ char smc[];
    uint32_t sb = smem_u32(smc);
    int t = threadIdx.x, w = t >> 5, lane = t & 31;

    // ---- load weights once: split hi/lo into padded [k][n] tiles ----
    for (int idx = t; idx < 4096; idx += 256) {
        int k = idx >> 6, n = idx & 63;
        uint32_t off = (uint32_t)(k * 72 + n) * 2;
        uint16_t hi, lo;
        split_bf16(w1[idx], hi, lo);
        *(uint16_t*)(smc + SM_W1H + off) = hi;
        *(uint16_t*)(smc + SM_W1L + off) = lo;
        split_bf16(w2[idx], hi, lo);
        *(uint16_t*)(smc + SM_W2H + off) = hi;
        *(uint16_t*)(smc + SM_W2L + off) = lo;
    }
    if (t < 64) {
        ((float*)(smc + SM_B1))[t] = b1[t];
        ((float*)(smc + SM_B2))[t] = b2[t];
    }
    __syncthreads();

    const float* b1s = (const float*)(smc + SM_B1);
    const float* b2s = (const float*)(smc + SM_B2);
    const float2* __restrict__ x2 = (const float2*)xin;

    const uint32_t aHiW = sb + SM_AH + (uint32_t)(w * 16 * ROWB);
    const uint32_t aLoW = sb + SM_AL + (uint32_t)(w * 16 * ROWB);
    char* aHiB = smc + SM_AH + w * 16 * ROWB;
    char* aLoB = smc + SM_AL + w * 16 * ROWB;

    int r0 = lane >> 2;
    int cq = (lane & 3) * 2;

    for (int tile = blockIdx.x; tile < NT; tile += gridDim.x) {
        int base = (tile << 7) + w * 16;

        // prefetch all 16 row degrees (one coalesced 64B load)
        int nn = base + (lane & 15);
        int degv = (lane < 16 && nn < N_NODES) ? g_cnt[nn] : 0;

        // ---- gather: z = x_i + sum_j x_j; all x-loads of a row issue together ----
        #pragma unroll 1
        for (int i = 0; i < 16; i++) {
            int n = base + i;
            if (n >= N_NODES) break;
            int deg = min(__shfl_sync(0xffffffffu, degv, i), CAP);
            const int* es = g_esrc + (n << 6);
            int esA = (lane < deg)      ? __ldg(es + lane)      : 0;
            int esB = (lane + 32 < deg) ? __ldg(es + lane + 32) : 0;
            float2 a = x2[n * 32 + lane];
            int e = 0;
            for (; e + 4 <= deg; e += 4) {
                int s0 = __shfl_sync(0xffffffffu, (e     < 32) ? esA : esB, (e)     & 31);
                int s1 = __shfl_sync(0xffffffffu, (e + 1 < 32) ? esA : esB, (e + 1) & 31);
                int s2 = __shfl_sync(0xffffffffu, (e + 2 < 32) ? esA : esB, (e + 2) & 31);
                int s3 = __shfl_sync(0xffffffffu, (e + 3 < 32) ? esA : esB, (e + 3) & 31);
                float2 v0 = __ldg(&x2[s0 * 32 + lane]);
                float2 v1 = __ldg(&x2[s1 * 32 + lane]);
                float2 v2 = __ldg(&x2[s2 * 32 + lane]);
                float2 v3 = __ldg(&x2[s3 * 32 + lane]);
                a.x += (v0.x + v1.x) + (v2.x + v3.x);
                a.y += (v0.y + v1.y) + (v2.y + v3.y);
            }
            for (; e < deg; e++) {
                int s = __shfl_sync(0xffffffffu, (e < 32) ? esA : esB, e & 31);
                float2 v = __ldg(&x2[s * 32 + lane]);
                a.x += v.x; a.y += v.y;
            }
            uint16_t h0, l0, h1, l1;
            split_bf16(a.x, h0, l0);
            split_bf16(a.y, h1, l1);
            *(uint32_t*)(aHiB + i * ROWB + lane * 4) = pack2(h0, h1);
            *(uint32_t*)(aLoB + i * ROWB + lane * 4) = pack2(l0, l1);
        }
        __syncwarp();

        // ---- layer 1 ----
        float acc[8][4];
        layer64(aHiW, aLoW, sb + SM_W1H, sb + SM_W1L, lane, acc);

        // epilogue 1: bias + relu, split back into own A rows
        #pragma unroll
        for (int j = 0; j < 8; j++) {
            int cb = j * 8 + cq;
            float v0 = fmaxf(acc[j][0] + b1s[cb],     0.f);
            float v1 = fmaxf(acc[j][1] + b1s[cb + 1], 0.f);
            float v2 = fmaxf(acc[j][2] + b1s[cb],     0.f);
            float v3 = fmaxf(acc[j][3] + b1s[cb + 1], 0.f);
            uint16_t h0, l0, h1, l1, h2, l2, h3, l3;
            split_bf16(v0, h0, l0); split_bf16(v1, h1, l1);
            split_bf16(v2, h2, l2); split_bf16(v3, h3, l3);
            *(uint32_t*)(aHiB + r0 * ROWB + cb * 2)       = pack2(h0, h1);
            *(uint32_t*)(aLoB + r0 * ROWB + cb * 2)       = pack2(l0, l1);
            *(uint32_t*)(aHiB + (r0 + 8) * ROWB + cb * 2) = pack2(h2, h3);
            *(uint32_t*)(aLoB + (r0 + 8) * ROWB + cb * 2) = pack2(l2, l3);
        }
        __syncwarp();

        // ---- layer 2 ----
        layer64(aHiW, aLoW, sb + SM_W2H, sb + SM_W2L, lane, acc);

        // epilogue 2: bias (+relu) -> gmem f32
        int n0 = base + r0;
        int n1 = n0 + 8;
        #pragma unroll
        for (int j = 0; j < 8; j++) {
            int cb = j * 8 + cq;
            float v0 = acc[j][0] + b2s[cb];
            float v1 = acc[j][1] + b2s[cb + 1];
            float v2 = acc[j][2] + b2s[cb];
            float v3 = acc[j][3] + b2s[cb + 1];
            if (RELU_OUT) {
                v0 = fmaxf(v0, 0.f); v1 = fmaxf(v1, 0.f);
                v2 = fmaxf(v2, 0.f); v3 = fmaxf(v3, 0.f);
            }
            if (n0 < N_NODES) *(float2*)(hout + n0 * 64 + cb) = make_float2(v0, v1);
            if (n1 < N_NODES) *(float2*)(hout + n1 * 64 + cb) = make_float2(v2, v3);
        }
        __syncwarp();
    }
}

// ---------------- pooling (+ re-zero g_cnt) ----------------
__global__ void __launch_bounds__(512) k_pool(const float* __restrict__ h) {
    for (int i = blockIdx.x * blockDim.x + threadIdx.x; i < N_NODES;
         i += gridDim.x * blockDim.x)
        g_cnt[i] = 0;

    __shared__ float ssum[8][64], smax[8][64];
    int g = blockIdx.x, t = threadIdx.x;
    int col = t & 63, ch = t >> 6;
    int beg = g_gb[g], end = g_gb[g + 1];
    float s = 0.f, m = -INFINITY;
    for (int i = beg + ch; i < end; i += 8) {
        float v = h[i * 64 + col];
        s += v; m = fmaxf(m, v);
    }
    ssum[ch][col] = s; smax[ch][col] = m;
    __syncthreads();
    if (t < 64) {
        float S = 0.f, M = -INFINITY;
        #pragma unroll
        for (int c = 0; c < 8; c++) { S += ssum[c][t]; M = fmaxf(M, smax[c][t]); }
        g_pool[g * 128 + t]      = S;
        g_pool[g * 128 + 64 + t] = M;
    }
}

// ---------------- head MLP ----------------
__device__ __forceinline__ float silu(float x) { return x / (1.f + expf(-x)); }

__global__ void __launch_bounds__(128) k_head(float* __restrict__ out,
        const float* __restrict__ w0, const float* __restrict__ b0,
        const float* __restrict__ w1, const float* __restrict__ b1,
        const float* __restrict__ w2, const float* __restrict__ b2,
        const float* __restrict__ w3, const float* __restrict__ b3,
        const float* __restrict__ w4, const float* __restrict__ b4) {
    __shared__ float bufA[128], bufB[128];
    int g = blockIdx.x, t = threadIdx.x;
    bufA[t] = g_pool[g * 128 + t];
    __syncthreads();
    {
        float a = b0[t];
        #pragma unroll 8
        for (int k = 0; k < 128; k++) a = fmaf(bufA[k], w0[k * 128 + t], a);
        bufB[t] = silu(a);
    }
    __syncthreads();
    if (t < 64) {
        float a = b1[t];
        #pragma unroll 8
        for (int k = 0; k < 128; k++) a = fmaf(bufB[k], w1[k * 64 + t], a);
        bufA[t] = silu(a);
    }
    __syncthreads();
    if (t < 32) {
        float a = b2[t];
        #pragma unroll 8
        for (int k = 0; k < 64; k++) a = fmaf(bufA[k], w2[k * 32 + t], a);
        bufB[t] = silu(a);
    }
    __syncthreads();
    if (t < 16) {
        float a = b3[t];
        #pragma unroll
        for (int k = 0; k < 32; k++) a = fmaf(bufB[k], w3[k * 16 + t], a);
        bufA[t] = silu(a);
    }
    __syncthreads();
    if (t == 0) {
        float a = b4[0];
        #pragma unroll
        for (int k = 0; k < 16; k++) a = fmaf(bufA[k], w4[k], a);
        out[g] = a;
    }
}

// ---------------- launch ----------------
extern "C" void kernel_launch(void* const* d_in, const int* in_sizes, int n_in,
                              void* d_out, int out_size) {
    const float* x     = (const float*)d_in[0];
    const int*   eidx  = (const int*)d_in[1];
    const int*   batch = (const int*)d_in[2];
    const float* c1w1 = (const float*)d_in[3];
    const float* c1b1 = (const float*)d_in[4];
    const float* c1w2 = (const float*)d_in[5];
    const float* c1b2 = (const float*)d_in[6];
    const float* c2w1 = (const float*)d_in[7];
    const float* c2b1 = (const float*)d_in[8];
    const float* c2w2 = (const float*)d_in[9];
    const float* c2b2 = (const float*)d_in[10];
    const float* hw0 = (const float*)d_in[11];
    const float* hb0 = (const float*)d_in[12];
    const float* hw1 = (const float*)d_in[13];
    const float* hb1 = (const float*)d_in[14];
    const float* hw2 = (const float*)d_in[15];
    const float* hb2 = (const float*)d_in[16];
    const float* hw3 = (const float*)d_in[17];
    const float* hb3 = (const float*)d_in[18];
    const float* hw4 = (const float*)d_in[19];
    const float* hb4 = (const float*)d_in[20];
    float* out = (float*)d_out;

    void *p1, *p2;
    cudaGetSymbolAddress(&p1, g_h1);
    cudaGetSymbolAddress(&p2, g_h2);
    float* h1 = (float*)p1;
    float* h2 = (float*)p2;

    static int attrDone = 0;
    if (!attrDone) {
        cudaFuncSetAttribute(k_conv<true>,  cudaFuncAttributeMaxDynamicSharedMemorySize, SM_TOTAL);
        cudaFuncSetAttribute(k_conv<false>, cudaFuncAttributeMaxDynamicSharedMemorySize, SM_TOTAL);
        attrDone = 1;
    }

    const int EB = (N_EDGES + 255) / 256;
    const int convGrid = 444;   // 3 CTAs/SM, grid-stride over 1563 tiles

    k_scatter<<<EB, 256>>>(eidx);                                               // 0
    k_gb<<<1, 256>>>(eidx, batch);                                              // 1
    k_conv<true><<<convGrid, 256, SM_TOTAL>>>(x, h1, c1w1, c1b1, c1w2, c1b2);   // 2
    k_conv<false><<<convGrid, 256, SM_TOTAL>>>(h1, h2, c2w1, c2b1, c2w2, c2b2); // 3
    k_pool<<<G, 512>>>(h2);                                                     // 4
    k_head<<<G, 128>>>(out, hw0, hb0, hw1, hb1, hw2, hb2, hw3, hb3, hw4, hb4);  // 5
}

// round 11
// speedup vs baseline: 2.2873x; 1.3196x over previous
#include <cuda_runtime.h>
#include <cuda_bf16.h>
#include <math.h>
#include <stdint.h>

#define N_NODES 200000
#define N_EDGES 1250000
#define G 128
#define CAP 64
#define NT 782             // ceil(N_NODES / 256)

// ---- dynamic smem byte offsets ----
#define SM_W1H  0
#define SM_W1L  9216
#define SM_W2H  18432
#define SM_W2L  27648
#define SM_AH   36864      // 256 rows x 144 B
#define SM_AL   73728
#define SM_B1   110592
#define SM_B2   110848
#define SM_TOTAL 111104
#define ROWB 144           // padded row stride in bytes (72 halves)

// ---------------- device scratch (zero-initialized at load) ----------------
__device__ int   g_cnt[N_NODES];          // degree cursor; zero at call start
__device__ int   g_esrc[N_NODES * CAP];
__device__ float g_h1[N_NODES * 64];
__device__ float g_h2[N_NODES * 64];
__device__ float g_pool[G * 2 * 64];
__device__ int   g_gb[G + 1];

// ---------------- helpers ----------------
__device__ __forceinline__ uint32_t smem_u32(const void* p) {
    uint32_t a;
    asm("{ .reg .u64 t; cvta.to.shared.u64 t, %1; cvt.u32.u64 %0, t; }" : "=r"(a) : "l"(p));
    return a;
}
__device__ __forceinline__ void ldm_x4(uint32_t addr, uint32_t r[4]) {
    asm volatile("ldmatrix.sync.aligned.m8n8.x4.shared.b16 {%0,%1,%2,%3}, [%4];"
                 : "=r"(r[0]), "=r"(r[1]), "=r"(r[2]), "=r"(r[3]) : "r"(addr));
}
__device__ __forceinline__ void ldm_x2t(uint32_t addr, uint32_t& b0, uint32_t& b1) {
    asm volatile("ldmatrix.sync.aligned.m8n8.x2.trans.shared.b16 {%0,%1}, [%2];"
                 : "=r"(b0), "=r"(b1) : "r"(addr));
}
__device__ __forceinline__ void mma_bf16(float* c, const uint32_t a[4],
                                         uint32_t b0, uint32_t b1) {
    asm volatile("mma.sync.aligned.m16n8k16.row.col.f32.bf16.bf16.f32 "
                 "{%0,%1,%2,%3}, {%4,%5,%6,%7}, {%8,%9}, {%0,%1,%2,%3};"
                 : "+f"(c[0]), "+f"(c[1]), "+f"(c[2]), "+f"(c[3])
                 : "r"(a[0]), "r"(a[1]), "r"(a[2]), "r"(a[3]), "r"(b0), "r"(b1));
}
__device__ __forceinline__ void split_bf16(float v, uint16_t& hi, uint16_t& lo) {
    __nv_bfloat16 h = __float2bfloat16(v);
    float r = v - __bfloat162float(h);
    __nv_bfloat16 l = __float2bfloat16(r);
    hi = __bfloat16_as_ushort(h);
    lo = __bfloat16_as_ushort(l);
}
// packed hi/lo split of a pair: hp = {lo16=bf16(v0), hi16=bf16(v1)}, lp = residuals
__device__ __forceinline__ void split2(float v0, float v1, uint32_t& hp, uint32_t& lp) {
    asm("cvt.rn.bf16x2.f32 %0, %1, %2;" : "=r"(hp) : "f"(v1), "f"(v0));
    float h0 = __uint_as_float(hp << 16);
    float h1 = __uint_as_float(hp & 0xffff0000u);
    float r0 = v0 - h0, r1 = v1 - h1;
    asm("cvt.rn.bf16x2.f32 %0, %1, %2;" : "=r"(lp) : "f"(r1), "f"(r0));
}

// one 64x64 GEMM layer: acc[8][4] = A(16x64, this warp's rows) @ W(64x64)
// 3-term hi/lo: Ah*Wh + Ah*Wl + Al*Wh
__device__ __forceinline__ void layer64(uint32_t aHi, uint32_t aLo,
                                        uint32_t wHi, uint32_t wLo,
                                        int lane, float acc[8][4]) {
    #pragma unroll
    for (int j = 0; j < 8; j++)
        #pragma unroll
        for (int q = 0; q < 4; q++) acc[j][q] = 0.f;

    uint32_t aOff = (uint32_t)(((lane & 7) + ((lane >> 3) & 1) * 8) * ROWB
                               + ((lane >> 4) * 8) * 2);
    #pragma unroll
    for (int kk = 0; kk < 4; kk++) {
        uint32_t ah[4], al[4];
        uint32_t ao = aOff + kk * 32;          // +16 halves per k-step
        ldm_x4(aHi + ao, ah);
        ldm_x4(aLo + ao, al);
        uint32_t brow = kk * 16 + (lane & 15);
        #pragma unroll
        for (int j = 0; j < 8; j++) {
            uint32_t bo = (brow * 72 + j * 8) * 2;
            uint32_t bh0, bh1, bl0, bl1;
            ldm_x2t(wHi + bo, bh0, bh1);
            ldm_x2t(wLo + bo, bl0, bl1);
            mma_bf16(acc[j], ah, bh0, bh1);
            mma_bf16(acc[j], ah, bl0, bl1);
            mma_bf16(acc[j], al, bh0, bh1);
        }
    }
}

// ---------------- scatter: bucket edges by dst ----------------
__global__ void k_scatter(const int* __restrict__ e32) {
    __shared__ int s_is64;
    if (threadIdx.x == 0) {
        int all0 = 1;
        #pragma unroll 1
        for (int i = 0; i < 64; i++)
            if (e32[2 * i + 1] != 0) { all0 = 0; break; }
        s_is64 = all0;
    }
    __syncthreads();
    int e = blockIdx.x * blockDim.x + threadIdx.x;
    if (e >= N_EDGES) return;
    int src, dst;
    if (s_is64) {
        const long long* p = (const long long*)e32;
        src = (int)p[e]; dst = (int)p[N_EDGES + e];
    } else {
        src = e32[e]; dst = e32[N_EDGES + e];
    }
    int pos = atomicAdd(&g_cnt[dst], 1);
    if (pos < CAP) g_esrc[(dst << 6) + pos] = src;
}

// ---------------- graph boundaries ----------------
__global__ void k_gb(const int* __restrict__ e32, const int* __restrict__ b32) {
    __shared__ int s_is64;
    if (threadIdx.x == 0) {
        int all0 = 1;
        #pragma unroll 1
        for (int i = 0; i < 64; i++)
            if (e32[2 * i + 1] != 0) { all0 = 0; break; }
        s_is64 = all0;
    }
    __syncthreads();
    int g = threadIdx.x;
    if (g > G) return;
    int lo = 0, hi = N_NODES;
    const long long* b64 = (const long long*)b32;
    while (lo < hi) {
        int mid = (lo + hi) >> 1;
        int bv = s_is64 ? (int)b64[mid] : b32[mid];
        if (bv < g) lo = mid + 1; else hi = mid;
    }
    g_gb[g] = lo;
}

// ---------------- fused GIN conv (warp-synchronous, pipelined gather) ----------------
template <bool RELU_OUT>
__global__ void __launch_bounds__(512, 2)
k_conv(const float* __restrict__ xin, float* __restrict__ hout,
       const float* __restrict__ w1, const float* __restrict__ b1,
       const float* __restrict__ w2, const float* __restrict__ b2) {
    extern __shared__ char smc[];
    uint32_t sb = smem_u32(smc);
    int t = threadIdx.x, w = t >> 5, lane = t & 31;

    // ---- load weights once: split hi/lo into padded [k][n] tiles ----
    for (int idx = t; idx < 4096; idx += 512) {
        int k = idx >> 6, n = idx & 63;
        uint32_t off = (uint32_t)(k * 72 + n) * 2;
        uint16_t hi, lo;
        split_bf16(w1[idx], hi, lo);
        *(uint16_t*)(smc + SM_W1H + off) = hi;
        *(uint16_t*)(smc + SM_W1L + off) = lo;
        split_bf16(w2[idx], hi, lo);
        *(uint16_t*)(smc + SM_W2H + off) = hi;
        *(uint16_t*)(smc + SM_W2L + off) = lo;
    }
    if (t < 64) {
        ((float*)(smc + SM_B1))[t] = b1[t];
        ((float*)(smc + SM_B2))[t] = b2[t];
    }
    __syncthreads();

    const float* b1s = (const float*)(smc + SM_B1);
    const float* b2s = (const float*)(smc + SM_B2);
    const float2* __restrict__ x2 = (const float2*)xin;

    const uint32_t aHiW = sb + SM_AH + (uint32_t)(w * 16 * ROWB);
    const uint32_t aLoW = sb + SM_AL + (uint32_t)(w * 16 * ROWB);
    char* aHiB = smc + SM_AH + w * 16 * ROWB;
    char* aLoB = smc + SM_AL + w * 16 * ROWB;

    int r0 = lane >> 2;
    int cq = (lane & 3) * 2;

    for (int tile = blockIdx.x; tile < NT; tile += gridDim.x) {
        int base = (tile << 8) + w * 16;
        int nrows = N_NODES - base;
        if (nrows > 16) nrows = 16;

        if (nrows > 0) {
            // prefetch all 16 row degrees (one coalesced load)
            int nn = base + (lane & 15);
            int degv = (lane < 16 && nn < N_NODES) ? g_cnt[nn] : 0;

            // prime the edge-list pipeline for row 0
            int degc = min(__shfl_sync(0xffffffffu, degv, 0), CAP);
            const int* es0 = g_esrc + ((long)base << 6);
            int eA = (lane < degc)      ? __ldg(es0 + lane)      : 0;
            int eB = (lane + 32 < degc) ? __ldg(es0 + lane + 32) : 0;

            #pragma unroll 1
            for (int i = 0; i < nrows; i++) {
                int n = base + i;
                int deg = degc, cA = eA, cB = eB;
                if (i + 1 < nrows) {   // prefetch next row's edge list
                    degc = min(__shfl_sync(0xffffffffu, degv, i + 1), CAP);
                    const int* es = g_esrc + ((long)(n + 1) << 6);
                    eA = (lane < degc)      ? __ldg(es + lane)      : 0;
                    eB = (lane + 32 < degc) ? __ldg(es + lane + 32) : 0;
                }
                float2 a = x2[n * 32 + lane];
                int e = 0;
                for (; e + 4 <= deg; e += 4) {
                    int s0 = __shfl_sync(0xffffffffu, (e     < 32) ? cA : cB, (e)     & 31);
                    int s1 = __shfl_sync(0xffffffffu, (e + 1 < 32) ? cA : cB, (e + 1) & 31);
                    int s2 = __shfl_sync(0xffffffffu, (e + 2 < 32) ? cA : cB, (e + 2) & 31);
                    int s3 = __shfl_sync(0xffffffffu, (e + 3 < 32) ? cA : cB, (e + 3) & 31);
                    float2 v0 = __ldg(&x2[s0 * 32 + lane]);
                    float2 v1 = __ldg(&x2[s1 * 32 + lane]);
                    float2 v2 = __ldg(&x2[s2 * 32 + lane]);
                    float2 v3 = __ldg(&x2[s3 * 32 + lane]);
                    a.x += (v0.x + v1.x) + (v2.x + v3.x);
                    a.y += (v0.y + v1.y) + (v2.y + v3.y);
                }
                for (; e < deg; e++) {
                    int s = __shfl_sync(0xffffffffu, (e < 32) ? cA : cB, e & 31);
                    float2 v = __ldg(&x2[s * 32 + lane]);
                    a.x += v.x; a.y += v.y;
                }
                uint32_t hp, lp;
                split2(a.x, a.y, hp, lp);
                *(uint32_t*)(aHiB + i * ROWB + lane * 4) = hp;
                *(uint32_t*)(aLoB + i * ROWB + lane * 4) = lp;
            }
        }
        __syncwarp();

        // ---- layer 1 ----
        float acc[8][4];
        layer64(aHiW, aLoW, sb + SM_W1H, sb + SM_W1L, lane, acc);

        // epilogue 1: bias + relu, split back into own A rows
        #pragma unroll
        for (int j = 0; j < 8; j++) {
            int cb = j * 8 + cq;
            float v0 = fmaxf(acc[j][0] + b1s[cb],     0.f);
            float v1 = fmaxf(acc[j][1] + b1s[cb + 1], 0.f);
            float v2 = fmaxf(acc[j][2] + b1s[cb],     0.f);
            float v3 = fmaxf(acc[j][3] + b1s[cb + 1], 0.f);
            uint32_t hp0, lp0, hp1, lp1;
            split2(v0, v1, hp0, lp0);
            split2(v2, v3, hp1, lp1);
            *(uint32_t*)(aHiB + r0 * ROWB + cb * 2)       = hp0;
            *(uint32_t*)(aLoB + r0 * ROWB + cb * 2)       = lp0;
            *(uint32_t*)(aHiB + (r0 + 8) * ROWB + cb * 2) = hp1;
            *(uint32_t*)(aLoB + (r0 + 8) * ROWB + cb * 2) = lp1;
        }
        __syncwarp();

        // ---- layer 2 ----
        layer64(aHiW, aLoW, sb + SM_W2H, sb + SM_W2L, lane, acc);

        // epilogue 2: bias (+relu) -> gmem f32
        int n0 = base + r0;
        int n1 = n0 + 8;
        #pragma unroll
        for (int j = 0; j < 8; j++) {
            int cb = j * 8 + cq;
            float v0 = acc[j][0] + b2s[cb];
            float v1 = acc[j][1] + b2s[cb + 1];
            float v2 = acc[j][2] + b2s[cb];
            float v3 = acc[j][3] + b2s[cb + 1];
            if (RELU_OUT) {
                v0 = fmaxf(v0, 0.f); v1 = fmaxf(v1, 0.f);
                v2 = fmaxf(v2, 0.f); v3 = fmaxf(v3, 0.f);
            }
            if (n0 < N_NODES) *(float2*)(hout + n0 * 64 + cb) = make_float2(v0, v1);
            if (n1 < N_NODES) *(float2*)(hout + n1 * 64 + cb) = make_float2(v2, v3);
        }
        __syncwarp();
    }
}

// ---------------- pooling (+ re-zero g_cnt) ----------------
__global__ void __launch_bounds__(512) k_pool(const float* __restrict__ h) {
    for (int i = blockIdx.x * blockDim.x + threadIdx.x; i < N_NODES;
         i += gridDim.x * blockDim.x)
        g_cnt[i] = 0;

    __shared__ float ssum[8][64], smax[8][64];
    int g = blockIdx.x, t = threadIdx.x;
    int col = t & 63, ch = t >> 6;
    int beg = g_gb[g], end = g_gb[g + 1];
    float s = 0.f, m = -INFINITY;
    for (int i = beg + ch; i < end; i += 8) {
        float v = h[i * 64 + col];
        s += v; m = fmaxf(m, v);
    }
    ssum[ch][col] = s; smax[ch][col] = m;
    __syncthreads();
    if (t < 64) {
        float S = 0.f, M = -INFINITY;
        #pragma unroll
        for (int c = 0; c < 8; c++) { S += ssum[c][t]; M = fmaxf(M, smax[c][t]); }
        g_pool[g * 128 + t]      = S;
        g_pool[g * 128 + 64 + t] = M;
    }
}

// ---------------- head MLP ----------------
__device__ __forceinline__ float silu(float x) { return x / (1.f + expf(-x)); }

__global__ void __launch_bounds__(128) k_head(float* __restrict__ out,
        const float* __restrict__ w0, const float* __restrict__ b0,
        const float* __restrict__ w1, const float* __restrict__ b1,
        const float* __restrict__ w2, const float* __restrict__ b2,
        const float* __restrict__ w3, const float* __restrict__ b3,
        const float* __restrict__ w4, const float* __restrict__ b4) {
    __shared__ float bufA[128], bufB[128];
    int g = blockIdx.x, t = threadIdx.x;
    bufA[t] = g_pool[g * 128 + t];
    __syncthreads();
    {
        float a = b0[t];
        #pragma unroll 8
        for (int k = 0; k < 128; k++) a = fmaf(bufA[k], w0[k * 128 + t], a);
        bufB[t] = silu(a);
    }
    __syncthreads();
    if (t < 64) {
        float a = b1[t];
        #pragma unroll 8
        for (int k = 0; k < 128; k++) a = fmaf(bufB[k], w1[k * 64 + t], a);
        bufA[t] = silu(a);
    }
    __syncthreads();
    if (t < 32) {
        float a = b2[t];
        #pragma unroll 8
        for (int k = 0; k < 64; k++) a = fmaf(bufA[k], w2[k * 32 + t], a);
        bufB[t] = silu(a);
    }
    __syncthreads();
    if (t < 16) {
        float a = b3[t];
        #pragma unroll
        for (int k = 0; k < 32; k++) a = fmaf(bufB[k], w3[k * 16 + t], a);
        bufA[t] = silu(a);
    }
    __syncthreads();
    if (t == 0) {
        float a = b4[0];
        #pragma unroll
        for (int k = 0; k < 16; k++) a = fmaf(bufA[k], w4[k], a);
        out[g] = a;
    }
}

// ---------------- launch ----------------
extern "C" void kernel_launch(void* const* d_in, const int* in_sizes, int n_in,
                              void* d_out, int out_size) {
    const float* x     = (const float*)d_in[0];
    const int*   eidx  = (const int*)d_in[1];
    const int*   batch = (const int*)d_in[2];
    const float* c1w1 = (const float*)d_in[3];
    const float* c1b1 = (const float*)d_in[4];
    const float* c1w2 = (const float*)d_in[5];
    const float* c1b2 = (const float*)d_in[6];
    const float* c2w1 = (const float*)d_in[7];
    const float* c2b1 = (const float*)d_in[8];
    const float* c2w2 = (const float*)d_in[9];
    const float* c2b2 = (const float*)d_in[10];
    const float* hw0 = (const float*)d_in[11];
    const float* hb0 = (const float*)d_in[12];
    const float* hw1 = (const float*)d_in[13];
    const float* hb1 = (const float*)d_in[14];
    const float* hw2 = (const float*)d_in[15];
    const float* hb2 = (const float*)d_in[16];
    const float* hw3 = (const float*)d_in[17];
    const float* hb3 = (const float*)d_in[18];
    const float* hw4 = (const float*)d_in[19];
    const float* hb4 = (const float*)d_in[20];
    float* out = (float*)d_out;

    void *p1, *p2;
    cudaGetSymbolAddress(&p1, g_h1);
    cudaGetSymbolAddress(&p2, g_h2);
    float* h1 = (float*)p1;
    float* h2 = (float*)p2;

    static int attrDone = 0;
    if (!attrDone) {
        cudaFuncSetAttribute(k_conv<true>,  cudaFuncAttributeMaxDynamicSharedMemorySize, SM_TOTAL);
        cudaFuncSetAttribute(k_conv<false>, cudaFuncAttributeMaxDynamicSharedMemorySize, SM_TOTAL);
        attrDone = 1;
    }

    const int EB = (N_EDGES + 255) / 256;
    const int convGrid = 296;   // 2 CTAs/SM, grid-stride over 782 tiles

    k_scatter<<<EB, 256>>>(eidx);                                               // 0
    k_gb<<<1, 256>>>(eidx, batch);                                              // 1
    k_conv<true><<<convGrid, 512, SM_TOTAL>>>(x, h1, c1w1, c1b1, c1w2, c1b2);   // 2
    k_conv<false><<<convGrid, 512, SM_TOTAL>>>(h1, h2, c2w1, c2b1, c2w2, c2b2); // 3
    k_pool<<<G, 512>>>(h2);                                                     // 4
    k_head<<<G, 128>>>(out, hw0, hb0, hw1, hb1, hw2, hb2, hw3, hb3, hw4, hb4);  // 5
}